// round 12
// baseline (speedup 1.0000x reference)
#include <cuda_runtime.h>

#define KCLS 19
#define Bn 4
#define Cn 64
#define HWn 262144      // 512*512
#define EPSf 1e-5f
#define COUNTf 6.0f

// ---- stats decomposition: 8 slices = (batch, channel-half); 56 blocks/slice
#define BLKS_PER_SLICE 56
#define NSLICE (Bn * 2)                       // 8
#define NBLK (NSLICE * BLKS_PER_SLICE)        // 448  -> ~3 blocks/SM
#define CHUNK 588                             // pixels per warp (mult of 4)
#define HKC (KCLS * 32)                       // 608 accum slots per block

#define TA 1024         // pixels per apply block

// ---- deterministic per-block partial scratch (no atomics anywhere) ----
__device__ float g_s1p[NBLK * HKC];
__device__ float g_s2p[NBLK * HKC];
__device__ float g_cntp[NBLK * KCLS];
__device__ float2 g_comb[Bn * KCLS * Cn];   // (scale, shift) per (b,k,c)

// ============================================================================
// Kernel 1: per-(b,k,c) sum / sumsq via per-warp SMEM float2 accumulators.
// Lane -> channel (half*32 + lane); warp streams pixels sequentially, so the
// class is warp-uniform. Each value does a branch-free LDS.64/FADD/FFMA/STS.64
// RMW into the warp's private 19x32 float2 table (lane-distinct banks ->
// conflict-free; warp-private -> no atomics, deterministic). 3 blocks/SM so
// the L1D carveout still holds the live streaming lines.
// ============================================================================
__global__ __launch_bounds__(256, 3) void stats_kernel(
    const float* __restrict__ x, const int* __restrict__ y)
{
    __shared__ float2 acc[8 * HKC];    // 38,912 B: per-warp private regions
    __shared__ float  scw[8 * KCLS];

    const int tid   = threadIdx.x;
    const int lane  = tid & 31;
    const int w     = tid >> 5;
    const int slice = blockIdx.x / BLKS_PER_SLICE;   // 0..7
    const int bslc  = blockIdx.x % BLKS_PER_SLICE;
    const int b     = slice >> 1;
    const int half  = slice & 1;
    const int c     = half * 32 + lane;

    const float* __restrict__ xrow = x + ((size_t)b * Cn + c) * HWn;
    const int*   __restrict__ yb   = y + (size_t)b * HWn;

    // zero all accumulator regions
    for (int i = tid; i < 8 * HKC; i += 256) acc[i] = make_float2(0.f, 0.f);
    __syncthreads();

    float2* __restrict__ myacc = acc + w * HKC + lane;   // index by k*32
    float cntf = 0.f;     // lane j (<19) counts class j over this warp's pixels

    const int i0   = (bslc * 8 + w) * CHUNK;
    const int pend = min(i0 + CHUNK, HWn);

#define UPD(KV, VV) { float2* _a = myacc + ((KV) << 5); float2 _d = *_a; \
                      _d.x += (VV); _d.y = fmaf((VV), (VV), _d.y); *_a = _d; }

    int p = i0;
    for (; p + 8 <= pend; p += 8) {
        int4   lb0 = *(const int4*)(yb + p);          // uniform broadcast
        int4   lb1 = *(const int4*)(yb + p + 4);
        float4 v0  = *(const float4*)(xrow + p);      // per-lane row stream
        float4 v1  = *(const float4*)(xrow + p + 4);
        cntf += (float)((lb0.x == lane) + (lb0.y == lane) +
                        (lb0.z == lane) + (lb0.w == lane) +
                        (lb1.x == lane) + (lb1.y == lane) +
                        (lb1.z == lane) + (lb1.w == lane));
        UPD(lb0.x, v0.x)  UPD(lb0.y, v0.y)  UPD(lb0.z, v0.z)  UPD(lb0.w, v0.w)
        UPD(lb1.x, v1.x)  UPD(lb1.y, v1.y)  UPD(lb1.z, v1.z)  UPD(lb1.w, v1.w)
    }
    for (; p < pend; p += 4) {
        int4   lb = *(const int4*)(yb + p);
        float4 v  = *(const float4*)(xrow + p);
        cntf += (float)((lb.x == lane) + (lb.y == lane) +
                        (lb.z == lane) + (lb.w == lane));
        UPD(lb.x, v.x)  UPD(lb.y, v.y)  UPD(lb.z, v.z)  UPD(lb.w, v.w)
    }
#undef UPD

    if (lane < KCLS) scw[w * KCLS + lane] = cntf;
    __syncthreads();

    // merge the 8 warp regions -> deterministic per-block partials
    for (int s = tid; s < HKC; s += 256) {
        float2 t = acc[s];
#pragma unroll
        for (int ww = 1; ww < 8; ww++) {
            float2 u = acc[ww * HKC + s];
            t.x += u.x; t.y += u.y;
        }
        g_s1p[(size_t)blockIdx.x * HKC + s] = t.x;
        g_s2p[(size_t)blockIdx.x * HKC + s] = t.y;
    }
    if (tid < KCLS) {
        float cs = 0.f;
#pragma unroll
        for (int ww = 0; ww < 8; ww++) cs += scw[ww * KCLS + tid];
        g_cntp[blockIdx.x * KCLS + tid] = cs;
    }
}

// ============================================================================
// Kernel 2: reduce partials -> (scale, shift); write style output tails.
// grid = 76 blocks (one per (b,k)), 64 threads (one per channel).
// Counts come from the half==0 slice only (both halves saw the same pixels).
// ============================================================================
__global__ void finalize_kernel(
    const float* __restrict__ style_means, const float* __restrict__ style_stds,
    float* __restrict__ dout)
{
    const int bk = blockIdx.x;            // 0..75
    const int c  = threadIdx.x;           // 0..63
    const int b  = bk / KCLS;
    const int k  = bk % KCLS;
    const int half  = c >> 5;
    const int lanec = c & 31;

    const int gbase  = (b * 2 + half) * BLKS_PER_SLICE;  // this channel's slice
    const int g0base = (b * 2) * BLKS_PER_SLICE;         // counts slice

    float s1 = 0.f, s2 = 0.f, cnt = 0.f;
    for (int blk = 0; blk < BLKS_PER_SLICE; blk++) {
        size_t g = (size_t)(gbase + blk) * HKC + k * 32 + lanec;
        s1  += g_s1p[g];
        s2  += g_s2p[g];
        cnt += g_cntp[(g0base + blk) * KCLS + k];
    }
    float cs   = fmaxf(cnt, 1.f);
    float mean = s1 / cs;
    float var  = (s2 - cs * mean * mean) / fmaxf(cnt - 1.f, 1.f);
    float stdc = sqrtf(fmaxf(var, 0.f)) + EPSf;
    bool valid = cnt > COUNTf;

    float sm = style_means[k * 64 + c];
    float ss = style_stds[k * 64 + c];
    float scale = valid ? (ss / stdc) : 1.f;
    float shift = valid ? (sm - mean * scale) : 0.f;
    g_comb[bk * 64 + c] = make_float2(scale, shift);

    // output tails: style_means_1dim | style_stds_1dim | valid_bk
    float* o1 = dout + (size_t)Bn * Cn * HWn;
    float* o2 = o1 + Bn * KCLS * Cn;
    float* o3 = o2 + Bn * KCLS * Cn;
    o1[bk * 64 + c] = valid ? sm : 0.f;
    o2[bk * 64 + c] = valid ? ss : 0.f;
    if (c == 0) o3[bk] = valid ? 1.f : 0.f;
}

// ============================================================================
// Kernel 3: apply. out = x * scale[b,lab,c] + shift[b,lab,c].
// Labels held in registers across the channel loop; (scale,shift) float2 table
// in SMEM with stride-67 padding (conflict-free label-indexed LDS.64).
// Pure float4 streaming otherwise.
// ============================================================================
__global__ __launch_bounds__(256) void apply_kernel(
    const float* __restrict__ x, const int* __restrict__ y,
    float* __restrict__ out)
{
    __shared__ float2 comb[KCLS * 67];

    const int tid = threadIdx.x;
    const int b   = blockIdx.x / (HWn / TA);
    const int tIn = blockIdx.x % (HWn / TA);
    const int p0  = tIn * TA;

    for (int i = tid; i < KCLS * Cn; i += 256) {
        int k = i >> 6, c = i & 63;
        comb[k * 67 + c] = g_comb[(b * KCLS + k) * 64 + c];
    }
    int4 lb = ((const int4*)(y + (size_t)b * HWn + p0))[tid];
    __syncthreads();

    const float* xb = x + (size_t)b * Cn * HWn + p0;
    float*       ob = out + (size_t)b * Cn * HWn + p0;

#pragma unroll 4
    for (int c = 0; c < Cn; c++) {
        float4 v = ((const float4*)(xb + (size_t)c * HWn))[tid];
        float2 t0 = comb[lb.x * 67 + c];
        float2 t1 = comb[lb.y * 67 + c];
        float2 t2 = comb[lb.z * 67 + c];
        float2 t3 = comb[lb.w * 67 + c];
        float4 r;
        r.x = fmaf(v.x, t0.x, t0.y);
        r.y = fmaf(v.y, t1.x, t1.y);
        r.z = fmaf(v.z, t2.x, t2.y);
        r.w = fmaf(v.w, t3.x, t3.y);
        ((float4*)(ob + (size_t)c * HWn))[tid] = r;
    }
}

// ============================================================================
extern "C" void kernel_launch(void* const* d_in, const int* in_sizes, int n_in,
                              void* d_out, int out_size)
{
    const float* x  = (const float*)d_in[0];   // x_content [4,64,512,512] f32
    const int*   y  = (const int*)d_in[1];     // y_content [4,512,512] i32
    const float* sm = (const float*)d_in[2];   // style_means [19,64] f32
    const float* ss = (const float*)d_in[3];   // style_stds  [19,64] f32
    float* out = (float*)d_out;

    stats_kernel<<<NBLK, 256>>>(x, y);
    finalize_kernel<<<Bn * KCLS, Cn>>>(sm, ss, out);
    apply_kernel<<<Bn * (HWn / TA), 256>>>(x, y, out);
}

// round 13
// speedup vs baseline: 1.0278x; 1.0278x over previous
#include <cuda_runtime.h>

#define KCLS 19
#define Bn 4
#define Cn 64
#define HWn 262144      // 512*512
#define EPSf 1e-5f
#define COUNTf 6.0f

// ---- stats decomposition: 8 slices = (batch, channel-half); 92 blocks/slice
#define BLKS_PER_SLICE 92
#define NSLICE (Bn * 2)                       // 8
#define NBLK (NSLICE * BLKS_PER_SLICE)        // 736 -> ~5 blocks/SM (smem-lim)
#define SWARPS 4                              // warps per stats block
#define CHUNK 720                             // pixels per warp (mult of 8)
#define HKC (KCLS * 32)                       // 608 accum slots per region

#define TA 1024         // pixels per apply block

// ---- deterministic per-block partial scratch (no atomics anywhere) ----
__device__ float g_s1p[NBLK * HKC];
__device__ float g_s2p[NBLK * HKC];
__device__ float g_cntp[NBLK * KCLS];
__device__ float2 g_comb[Bn * KCLS * Cn];   // (scale, shift) per (b,k,c)

// ============================================================================
// Kernel 1: per-(b,k,c) sum/sumsq via DUAL per-warp SMEM float2 tables.
// Lane -> channel (half*32 + lane); warp streams pixels sequentially, class is
// warp-uniform. Even pixels bin into table slot 0, odd pixels into slot 1, so
// each 2-pixel batch does LDS,LDS -> arith -> STS,STS with NO intra-batch
// aliasing (different tables) -> ptxas keeps both loads in flight; one 29-cyc
// LDS exposure per 2 pixels instead of a serial chain per pixel (the R11 bug).
// Cross-batch ordering is free: in-order per-warp LSU, STS has no result
// latency. Branch-free, atomic-free, deterministic.
// ============================================================================
__global__ __launch_bounds__(128, 5) void stats_kernel(
    const float* __restrict__ x, const int* __restrict__ y)
{
    __shared__ float2 acc[SWARPS * 2 * HKC];   // 38,912 B: per-warp dual tables
    __shared__ float  scw[SWARPS * KCLS];

    const int tid   = threadIdx.x;
    const int lane  = tid & 31;
    const int w     = tid >> 5;
    const int slice = blockIdx.x / BLKS_PER_SLICE;   // 0..7
    const int bslc  = blockIdx.x % BLKS_PER_SLICE;
    const int b     = slice >> 1;
    const int half  = slice & 1;
    const int c     = half * 32 + lane;

    const float* __restrict__ xrow = x + ((size_t)b * Cn + c) * HWn;
    const int*   __restrict__ yb   = y + (size_t)b * HWn;

    for (int i = tid; i < SWARPS * 2 * HKC; i += 128) acc[i] = make_float2(0.f, 0.f);
    __syncthreads();

    float2* __restrict__ t0 = acc + (w * 2 + 0) * HKC + lane;  // even pixels
    float2* __restrict__ t1 = acc + (w * 2 + 1) * HKC + lane;  // odd pixels
    float cntf = 0.f;     // lane j (<19) counts class j over this warp's pixels

    const int i0   = (bslc * SWARPS + w) * CHUNK;
    const int pend = min(i0 + CHUNK, HWn);

    // one 2-pixel batch: ke/ko warp-uniform labels, ve/vo this lane's values
#define BATCH2(KE, VE, KO, VO) { \
        float2* _a = t0 + ((KE) << 5); \
        float2* _b = t1 + ((KO) << 5); \
        float2 _da = *_a; \
        float2 _db = *_b; \
        _da.x += (VE); _da.y = fmaf((VE), (VE), _da.y); \
        _db.x += (VO); _db.y = fmaf((VO), (VO), _db.y); \
        *_a = _da; *_b = _db; }

    for (int p = i0; p < pend; p += 8) {
        int4   lb0 = *(const int4*)(yb + p);          // uniform broadcast
        int4   lb1 = *(const int4*)(yb + p + 4);
        float4 v0  = *(const float4*)(xrow + p);      // per-lane row stream
        float4 v1  = *(const float4*)(xrow + p + 4);
        cntf += (float)((lb0.x == lane) + (lb0.y == lane) +
                        (lb0.z == lane) + (lb0.w == lane) +
                        (lb1.x == lane) + (lb1.y == lane) +
                        (lb1.z == lane) + (lb1.w == lane));
        BATCH2(lb0.x, v0.x, lb0.y, v0.y)
        BATCH2(lb0.z, v0.z, lb0.w, v0.w)
        BATCH2(lb1.x, v1.x, lb1.y, v1.y)
        BATCH2(lb1.z, v1.z, lb1.w, v1.w)
    }
#undef BATCH2

    if (lane < KCLS) scw[w * KCLS + lane] = cntf;
    __syncthreads();

    // merge the 8 regions (4 warps x 2 slots) -> deterministic block partials
    for (int s = tid; s < HKC; s += 128) {
        float2 t = acc[s];
#pragma unroll
        for (int r = 1; r < SWARPS * 2; r++) {
            float2 u = acc[r * HKC + s];
            t.x += u.x; t.y += u.y;
        }
        g_s1p[(size_t)blockIdx.x * HKC + s] = t.x;
        g_s2p[(size_t)blockIdx.x * HKC + s] = t.y;
    }
    if (tid < KCLS) {
        float cs = 0.f;
#pragma unroll
        for (int ww = 0; ww < SWARPS; ww++) cs += scw[ww * KCLS + tid];
        g_cntp[blockIdx.x * KCLS + tid] = cs;
    }
}

// ============================================================================
// Kernel 2: reduce partials -> (scale, shift); write style output tails.
// grid = 76 blocks (one per (b,k)), 64 threads (one per channel).
// Counts come from the half==0 slice only (both halves saw the same pixels).
// ============================================================================
__global__ void finalize_kernel(
    const float* __restrict__ style_means, const float* __restrict__ style_stds,
    float* __restrict__ dout)
{
    const int bk = blockIdx.x;            // 0..75
    const int c  = threadIdx.x;           // 0..63
    const int b  = bk / KCLS;
    const int k  = bk % KCLS;
    const int half  = c >> 5;
    const int lanec = c & 31;

    const int gbase  = (b * 2 + half) * BLKS_PER_SLICE;  // this channel's slice
    const int g0base = (b * 2) * BLKS_PER_SLICE;         // counts slice

    float s1 = 0.f, s2 = 0.f, cnt = 0.f;
    for (int blk = 0; blk < BLKS_PER_SLICE; blk++) {
        size_t g = (size_t)(gbase + blk) * HKC + k * 32 + lanec;
        s1  += g_s1p[g];
        s2  += g_s2p[g];
        cnt += g_cntp[(g0base + blk) * KCLS + k];
    }
    float cs   = fmaxf(cnt, 1.f);
    float mean = s1 / cs;
    float var  = (s2 - cs * mean * mean) / fmaxf(cnt - 1.f, 1.f);
    float stdc = sqrtf(fmaxf(var, 0.f)) + EPSf;
    bool valid = cnt > COUNTf;

    float sm = style_means[k * 64 + c];
    float ss = style_stds[k * 64 + c];
    float scale = valid ? (ss / stdc) : 1.f;
    float shift = valid ? (sm - mean * scale) : 0.f;
    g_comb[bk * 64 + c] = make_float2(scale, shift);

    // output tails: style_means_1dim | style_stds_1dim | valid_bk
    float* o1 = dout + (size_t)Bn * Cn * HWn;
    float* o2 = o1 + Bn * KCLS * Cn;
    float* o3 = o2 + Bn * KCLS * Cn;
    o1[bk * 64 + c] = valid ? sm : 0.f;
    o2[bk * 64 + c] = valid ? ss : 0.f;
    if (c == 0) o3[bk] = valid ? 1.f : 0.f;
}

// ============================================================================
// Kernel 3: apply. out = x * scale[b,lab,c] + shift[b,lab,c].
// Labels held in registers across the channel loop; (scale,shift) float2 table
// in SMEM with stride-67 padding (conflict-free label-indexed LDS.64).
// Pure float4 streaming otherwise.
// ============================================================================
__global__ __launch_bounds__(256) void apply_kernel(
    const float* __restrict__ x, const int* __restrict__ y,
    float* __restrict__ out)
{
    __shared__ float2 comb[KCLS * 67];

    const int tid = threadIdx.x;
    const int b   = blockIdx.x / (HWn / TA);
    const int tIn = blockIdx.x % (HWn / TA);
    const int p0  = tIn * TA;

    for (int i = tid; i < KCLS * Cn; i += 256) {
        int k = i >> 6, c = i & 63;
        comb[k * 67 + c] = g_comb[(b * KCLS + k) * 64 + c];
    }
    int4 lb = ((const int4*)(y + (size_t)b * HWn + p0))[tid];
    __syncthreads();

    const float* xb = x + (size_t)b * Cn * HWn + p0;
    float*       ob = out + (size_t)b * Cn * HWn + p0;

#pragma unroll 4
    for (int c = 0; c < Cn; c++) {
        float4 v = ((const float4*)(xb + (size_t)c * HWn))[tid];
        float2 t0 = comb[lb.x * 67 + c];
        float2 t1 = comb[lb.y * 67 + c];
        float2 t2 = comb[lb.z * 67 + c];
        float2 t3 = comb[lb.w * 67 + c];
        float4 r;
        r.x = fmaf(v.x, t0.x, t0.y);
        r.y = fmaf(v.y, t1.x, t1.y);
        r.z = fmaf(v.z, t2.x, t2.y);
        r.w = fmaf(v.w, t3.x, t3.y);
        ((float4*)(ob + (size_t)c * HWn))[tid] = r;
    }
}

// ============================================================================
extern "C" void kernel_launch(void* const* d_in, const int* in_sizes, int n_in,
                              void* d_out, int out_size)
{
    const float* x  = (const float*)d_in[0];   // x_content [4,64,512,512] f32
    const int*   y  = (const int*)d_in[1];     // y_content [4,512,512] i32
    const float* sm = (const float*)d_in[2];   // style_means [19,64] f32
    const float* ss = (const float*)d_in[3];   // style_stds  [19,64] f32
    float* out = (float*)d_out;

    stats_kernel<<<NBLK, 128>>>(x, y);
    finalize_kernel<<<Bn * KCLS, Cn>>>(sm, ss, out);
    apply_kernel<<<Bn * (HWn / TA), 256>>>(x, y, out);
}

// round 14
// speedup vs baseline: 1.1768x; 1.1450x over previous
#include <cuda_runtime.h>

#define KCLS 19
#define Bn 4
#define Cn 64
#define HWn 262144      // 512*512
#define EPSf 1e-5f
#define COUNTf 6.0f

// ---- stats: 111 blocks per batch, 64-px tiles staged through SMEM ----
#define BLKS_PER_B 111
#define NBLK (Bn * BLKS_PER_B)    // 444 = 3 blocks/SM, one wave
#define TPX 64                    // pixels per tile
#define NTILES (HWn / TPX)        // 4096 tiles per batch
#define PAD 65                    // tile row stride (odd -> conflict-free)
#define BKC (KCLS * Cn)           // 1216

#define TA 1024         // pixels per apply block

// ---- deterministic per-block partial scratch (no atomics anywhere) ----
__device__ float g_s1p[NBLK * BKC];
__device__ float g_s2p[NBLK * BKC];
__device__ float g_cntp[NBLK * KCLS];
__device__ float2 g_comb[Bn * KCLS * Cn];   // (scale, shift) per (b,k,c)

// ============================================================================
// Kernel 1: per-(b,k,c) sum/sumsq. Coalesced LDG into registers, STS into a
// pad-65 SMEM tile (64ch x 64px), then warp-uniform-class register binning:
// warp w: half = w>>2 (channels half*32+lane), psub = w&3 (16 pixels).
// Class read from SMEM labels is warp-uniform -> 19-way switch into
// compile-time-indexed register accumulators (38 regs). This kills the
// 32-line-per-LDG L1 wavefront scatter that bound R7/R11/R13.
// Register-buffered pipeline: LDG(t+1) issued before compute(t).
// ============================================================================
__global__ __launch_bounds__(256, 3) void stats_kernel(
    const float* __restrict__ x, const int* __restrict__ y)
{
    __shared__ float xs[64 * PAD];     // value tile [c][p] at c*PAD+p
    __shared__ int4  ls4[TPX / 4];     // 64 labels
    __shared__ float msum[BKC];
    __shared__ float msq[BKC];
    __shared__ float scnt[KCLS];

    const int tid  = threadIdx.x;
    const int lane = tid & 31;
    const int w    = tid >> 5;
    const int half = w >> 2;           // 0: ch 0-31, 1: ch 32-63
    const int psub = w & 3;            // 16-pixel subset within tile
    const int ch   = half * 32 + lane;
    const int b    = blockIdx.x / BLKS_PER_B;
    const int tb   = blockIdx.x % BLKS_PER_B;

    const float* __restrict__ xb = x + (size_t)b * Cn * HWn;
    const int*   __restrict__ yb = y + (size_t)b * HWn;

    // staging roles: thread handles float4 chunks m = tid + k*256 (k=0..3),
    // chunk m: row c = m>>4, j = m&15 -> gmem xb[c*HW + t*64 + 4j]
    const int c0 = tid >> 4;           // row for k=0 chunk (tid + 0*256)
    const int j0 = tid & 15;

    float S[KCLS], Q[KCLS];
#pragma unroll
    for (int j = 0; j < KCLS; j++) { S[j] = 0.f; Q[j] = 0.f; }
    float cntf = 0.f;

    for (int i = tid; i < BKC; i += 256) { msum[i] = 0.f; msq[i] = 0.f; }
    if (tid < KCLS) scnt[tid] = 0.f;

    // ---- prologue: load tile tb into registers ----
    float4 vb0, vb1, vb2, vb3;
    int4 lb;
    {
        const float* base = xb + (size_t)tb * TPX;
        vb0 = *(const float4*)(base + (size_t)(c0     ) * HWn + 4 * j0);
        vb1 = *(const float4*)(base + (size_t)(c0 + 16) * HWn + 4 * j0);
        vb2 = *(const float4*)(base + (size_t)(c0 + 32) * HWn + 4 * j0);
        vb3 = *(const float4*)(base + (size_t)(c0 + 48) * HWn + 4 * j0);
        if (tid < 16) lb = ((const int4*)(yb + tb * TPX))[tid];
    }

#define CASE1(j) case j: S[j] += v; Q[j] = fmaf(v, v, Q[j]); break;

    for (int t = tb; t < NTILES; ) {
        __syncthreads();   // previous compute done (and init done on iter 0)
        // ---- store staged regs into tile ----
        {
            int base0 = (c0     ) * PAD + 4 * j0;
            int base1 = (c0 + 16) * PAD + 4 * j0;
            int base2 = (c0 + 32) * PAD + 4 * j0;
            int base3 = (c0 + 48) * PAD + 4 * j0;
            xs[base0] = vb0.x; xs[base0+1] = vb0.y; xs[base0+2] = vb0.z; xs[base0+3] = vb0.w;
            xs[base1] = vb1.x; xs[base1+1] = vb1.y; xs[base1+2] = vb1.z; xs[base1+3] = vb1.w;
            xs[base2] = vb2.x; xs[base2+1] = vb2.y; xs[base2+2] = vb2.z; xs[base2+3] = vb2.w;
            xs[base3] = vb3.x; xs[base3+1] = vb3.y; xs[base3+2] = vb3.z; xs[base3+3] = vb3.w;
            if (tid < 16) ls4[tid] = lb;
        }
        __syncthreads();

        // ---- issue next tile's loads early (overlap with compute) ----
        int tn = t + BLKS_PER_B;
        if (tn < NTILES) {
            const float* base = xb + (size_t)tn * TPX;
            vb0 = *(const float4*)(base + (size_t)(c0     ) * HWn + 4 * j0);
            vb1 = *(const float4*)(base + (size_t)(c0 + 16) * HWn + 4 * j0);
            vb2 = *(const float4*)(base + (size_t)(c0 + 32) * HWn + 4 * j0);
            vb3 = *(const float4*)(base + (size_t)(c0 + 48) * HWn + 4 * j0);
            if (tid < 16) lb = ((const int4*)(yb + tn * TPX))[tid];
        }

        // ---- compute: 16 pixels, class warp-uniform, register binning ----
        const int* lsw = (const int*)ls4;
#pragma unroll
        for (int i = 0; i < 16; i++) {
            int p = psub * 16 + i;
            int k = lsw[p];                      // warp-uniform broadcast
            float v = xs[ch * PAD + p];          // conflict-free (pad 65)
            if (half == 0) cntf += (k == lane) ? 1.f : 0.f;
            switch (k) {
                CASE1(0)  CASE1(1)  CASE1(2)  CASE1(3)  CASE1(4)
                CASE1(5)  CASE1(6)  CASE1(7)  CASE1(8)  CASE1(9)
                CASE1(10) CASE1(11) CASE1(12) CASE1(13) CASE1(14)
                CASE1(15) CASE1(16) CASE1(17) CASE1(18)
                default: break;
            }
        }
        t = tn;
    }
#undef CASE1

    // ---- block-level merge: serialized warp phases, no atomics ----
    __syncthreads();
    for (int ww = 0; ww < 8; ww++) {
        if (w == ww) {
#pragma unroll
            for (int j = 0; j < KCLS; j++) {
                msum[j * 64 + ch] += S[j];
                msq [j * 64 + ch] += Q[j];
            }
            if (half == 0 && lane < KCLS) scnt[lane] += cntf;
        }
        __syncthreads();
    }
    float* s1p = g_s1p + (size_t)blockIdx.x * BKC;
    float* s2p = g_s2p + (size_t)blockIdx.x * BKC;
    for (int i = tid; i < BKC; i += 256) { s1p[i] = msum[i]; s2p[i] = msq[i]; }
    if (tid < KCLS) g_cntp[blockIdx.x * KCLS + tid] = scnt[tid];
}

// ============================================================================
// Kernel 2: reduce partials -> (scale, shift); write style output tails.
// grid = 76 blocks (one per (b,k)), 64 threads (one per channel).
// ============================================================================
__global__ void finalize_kernel(
    const float* __restrict__ style_means, const float* __restrict__ style_stds,
    float* __restrict__ dout)
{
    const int bk = blockIdx.x;            // 0..75
    const int c  = threadIdx.x;           // 0..63
    const int b  = bk / KCLS;
    const int k  = bk % KCLS;

    float s1 = 0.f, s2 = 0.f, cnt = 0.f;
    const int gbase = b * BLKS_PER_B;
    for (int blk = 0; blk < BLKS_PER_B; blk++) {
        size_t g = (size_t)(gbase + blk) * BKC + k * 64 + c;
        s1  += g_s1p[g];
        s2  += g_s2p[g];
        cnt += g_cntp[(gbase + blk) * KCLS + k];
    }
    float cs   = fmaxf(cnt, 1.f);
    float mean = s1 / cs;
    float var  = (s2 - cs * mean * mean) / fmaxf(cnt - 1.f, 1.f);
    float stdc = sqrtf(fmaxf(var, 0.f)) + EPSf;
    bool valid = cnt > COUNTf;

    float sm = style_means[k * 64 + c];
    float ss = style_stds[k * 64 + c];
    float scale = valid ? (ss / stdc) : 1.f;
    float shift = valid ? (sm - mean * scale) : 0.f;
    g_comb[bk * 64 + c] = make_float2(scale, shift);

    // output tails: style_means_1dim | style_stds_1dim | valid_bk
    float* o1 = dout + (size_t)Bn * Cn * HWn;
    float* o2 = o1 + Bn * KCLS * Cn;
    float* o3 = o2 + Bn * KCLS * Cn;
    o1[bk * 64 + c] = valid ? sm : 0.f;
    o2[bk * 64 + c] = valid ? ss : 0.f;
    if (c == 0) o3[bk] = valid ? 1.f : 0.f;
}

// ============================================================================
// Kernel 3: apply. out = x * scale[b,lab,c] + shift[b,lab,c].
// Labels held in registers across the channel loop; (scale,shift) float2 table
// in SMEM with stride-67 padding (conflict-free label-indexed LDS.64).
// Pure float4 streaming otherwise.
// ============================================================================
__global__ __launch_bounds__(256) void apply_kernel(
    const float* __restrict__ x, const int* __restrict__ y,
    float* __restrict__ out)
{
    __shared__ float2 comb[KCLS * 67];

    const int tid = threadIdx.x;
    const int b   = blockIdx.x / (HWn / TA);
    const int tIn = blockIdx.x % (HWn / TA);
    const int p0  = tIn * TA;

    for (int i = tid; i < KCLS * Cn; i += 256) {
        int k = i >> 6, c = i & 63;
        comb[k * 67 + c] = g_comb[(b * KCLS + k) * 64 + c];
    }
    int4 lb = ((const int4*)(y + (size_t)b * HWn + p0))[tid];
    __syncthreads();

    const float* xb = x + (size_t)b * Cn * HWn + p0;
    float*       ob = out + (size_t)b * Cn * HWn + p0;

#pragma unroll 4
    for (int c = 0; c < Cn; c++) {
        float4 v = ((const float4*)(xb + (size_t)c * HWn))[tid];
        float2 t0 = comb[lb.x * 67 + c];
        float2 t1 = comb[lb.y * 67 + c];
        float2 t2 = comb[lb.z * 67 + c];
        float2 t3 = comb[lb.w * 67 + c];
        float4 r;
        r.x = fmaf(v.x, t0.x, t0.y);
        r.y = fmaf(v.y, t1.x, t1.y);
        r.z = fmaf(v.z, t2.x, t2.y);
        r.w = fmaf(v.w, t3.x, t3.y);
        ((float4*)(ob + (size_t)c * HWn))[tid] = r;
    }
}

// ============================================================================
extern "C" void kernel_launch(void* const* d_in, const int* in_sizes, int n_in,
                              void* d_out, int out_size)
{
    const float* x  = (const float*)d_in[0];   // x_content [4,64,512,512] f32
    const int*   y  = (const int*)d_in[1];     // y_content [4,512,512] i32
    const float* sm = (const float*)d_in[2];   // style_means [19,64] f32
    const float* ss = (const float*)d_in[3];   // style_stds  [19,64] f32
    float* out = (float*)d_out;

    stats_kernel<<<NBLK, 256>>>(x, y);
    finalize_kernel<<<Bn * KCLS, Cn>>>(sm, ss, out);
    apply_kernel<<<Bn * (HWn / TA), 256>>>(x, y, out);
}